// round 3
// baseline (speedup 1.0000x reference)
#include <cuda_runtime.h>

// Problem constants
#define B_SZ 8
#define T_SZ 2048
#define C_SZ 1024
#define H_SZ 128
#define M_TOT (B_SZ * T_SZ)   // 16384 rows for QKV GEMM

// Scratch for projected q, k, v (allocation-free rule: __device__ globals)
__device__ float g_q[M_TOT * H_SZ];
__device__ float g_k[M_TOT * H_SZ];
__device__ float g_v[M_TOT * H_SZ];

// ---------------------------------------------------------------------------
// QKV projection: out = X[16384,1024] @ W[1024,128] + b  (one of q/k/v per blockIdx.y)
// 128x128 block tile, K-step 32, 256 threads, 8x8 register micro-tile.
// ---------------------------------------------------------------------------
__global__ __launch_bounds__(256) void qkv_kernel(
    const float* __restrict__ X,
    const float* __restrict__ Wq, const float* __restrict__ bq,
    const float* __restrict__ Wk, const float* __restrict__ bk,
    const float* __restrict__ Wv, const float* __restrict__ bv)
{
    __shared__ float Xs[32][132];   // [k][m], padded stride 132 (mult of 4 for float4)
    __shared__ float Ws[32][128];   // [k][n]

    const float* W;
    const float* bias;
    float* out;
    if (blockIdx.y == 0)      { W = Wq; bias = bq; out = g_q; }
    else if (blockIdx.y == 1) { W = Wk; bias = bk; out = g_k; }
    else                      { W = Wv; bias = bv; out = g_v; }

    const int tid = threadIdx.x;
    const int tx = tid & 15;
    const int ty = tid >> 4;
    const int m0 = blockIdx.x * 128;

    float acc[8][8];
    #pragma unroll
    for (int i = 0; i < 8; i++)
        #pragma unroll
        for (int j = 0; j < 8; j++) acc[i][j] = 0.f;

    for (int k0 = 0; k0 < C_SZ; k0 += 32) {
        // Load X tile (128 rows x 32 k), store transposed into Xs[k][m]
        #pragma unroll
        for (int i = 0; i < 4; i++) {
            int row = i * 32 + (tid >> 3);
            int col = (tid & 7) * 4;
            float4 xv = *(const float4*)&X[(size_t)(m0 + row) * C_SZ + k0 + col];
            Xs[col + 0][row] = xv.x;
            Xs[col + 1][row] = xv.y;
            Xs[col + 2][row] = xv.z;
            Xs[col + 3][row] = xv.w;
        }
        // Load W tile (32 k x 128 n) directly
        #pragma unroll
        for (int i = 0; i < 4; i++) {
            int row = i * 8 + (tid >> 5);
            int col = (tid & 31) * 4;
            *(float4*)&Ws[row][col] =
                *(const float4*)&W[(size_t)(k0 + row) * H_SZ + col];
        }
        __syncthreads();

        #pragma unroll
        for (int kk = 0; kk < 32; kk++) {
            float a[8], b[8];
            *(float4*)&a[0] = *(const float4*)&Xs[kk][ty * 8];
            *(float4*)&a[4] = *(const float4*)&Xs[kk][ty * 8 + 4];
            *(float4*)&b[0] = *(const float4*)&Ws[kk][tx * 8];
            *(float4*)&b[4] = *(const float4*)&Ws[kk][tx * 8 + 4];
            #pragma unroll
            for (int i = 0; i < 8; i++)
                #pragma unroll
                for (int j = 0; j < 8; j++)
                    acc[i][j] += a[i] * b[j];
        }
        __syncthreads();
    }

    #pragma unroll
    for (int i = 0; i < 8; i++) {
        int row = m0 + ty * 8 + i;
        #pragma unroll
        for (int j = 0; j < 8; j += 4) {
            float4 o;
            o.x = acc[i][j + 0] + bias[tx * 8 + j + 0];
            o.y = acc[i][j + 1] + bias[tx * 8 + j + 1];
            o.z = acc[i][j + 2] + bias[tx * 8 + j + 2];
            o.w = acc[i][j + 3] + bias[tx * 8 + j + 3];
            *(float4*)&out[(size_t)row * H_SZ + tx * 8 + j] = o;
        }
    }
}

// ---------------------------------------------------------------------------
// Flash attention with online softmax.
// One CTA per (q-tile of 64 rows, batch). 256 threads = 16x16.
// Heavy q-tiles are mapped to LOW blockIdx.x so they launch in wave 1 and the
// cheap tiles backfill the tail (triangular-work balancing).
// Smem: Qs[64][128] | KVs (Kt[128][68] union V[64][128]) | Ps[64][68]
// ---------------------------------------------------------------------------
#define BM 64
#define BN 64
#define KT_STRIDE 68
#define P_STRIDE 68
#define ATTN_SMEM_FLOATS (BM * H_SZ + H_SZ * KT_STRIDE + BM * P_STRIDE)
#define ATTN_SMEM_BYTES (ATTN_SMEM_FLOATS * 4)

__global__ __launch_bounds__(256) void attn_kernel(float* __restrict__ out)
{
    extern __shared__ float sm[];
    float* Qs  = sm;                         // [64][128]
    float* KVs = Qs + BM * H_SZ;             // Kt[128][68]  or  V[64][128]
    float* Ps  = KVs + H_SZ * KT_STRIDE;     // [64][68]

    const int tid = threadIdx.x;
    const int tx = tid & 15;
    const int ty = tid >> 4;
    // Heaviest tiles first: blockIdx.x = 0 -> qtile = last (most K tiles)
    const int qtile = (int)gridDim.x - 1 - (int)blockIdx.x;
    const int b = blockIdx.y;
    const int q0 = qtile * BM;
    const float scale = 1.0f / 32.0f;        // C^-0.5, C=1024

    // Load Q tile, pre-scaled
    const float* qbase = g_q + (size_t)(b * T_SZ + q0) * H_SZ;
    #pragma unroll
    for (int i = 0; i < 8; i++) {
        int r = i * 8 + (tid >> 5);
        int c = (tid & 31) * 4;
        float4 qv = *(const float4*)&qbase[(size_t)r * H_SZ + c];
        qv.x *= scale; qv.y *= scale; qv.z *= scale; qv.w *= scale;
        *(float4*)&Qs[r * H_SZ + c] = qv;
    }

    float m_i[4], l_i[4], acc[4][8];
    #pragma unroll
    for (int i = 0; i < 4; i++) {
        m_i[i] = -1e30f;
        l_i[i] = 0.f;
        #pragma unroll
        for (int j = 0; j < 8; j++) acc[i][j] = 0.f;
    }

    const int w = tid >> 5;        // warp id 0..7
    const int lane = tid & 31;

    for (int kt = 0; kt <= qtile; kt++) {
        __syncthreads();  // prior PV reads of KVs/Ps done; also covers Q load on iter 0

        // ---- Load K tile transposed: Kt[c][n], stride 68 ----
        {
            const float* kbase = g_k + (size_t)(b * T_SZ + kt * BN) * H_SZ;
            int n  = w * 8 + (lane & 7);     // token within tile
            int cg = (lane >> 3) * 4;        // 0,4,8,12
            #pragma unroll
            for (int i = 0; i < 8; i++) {
                int c = cg + i * 16;
                float4 kv = *(const float4*)&kbase[(size_t)n * H_SZ + c];
                KVs[(c + 0) * KT_STRIDE + n] = kv.x;
                KVs[(c + 1) * KT_STRIDE + n] = kv.y;
                KVs[(c + 2) * KT_STRIDE + n] = kv.z;
                KVs[(c + 3) * KT_STRIDE + n] = kv.w;
            }
        }
        __syncthreads();

        // ---- S = Q * K^T (4x4 per thread) ----
        float s[4][4];
        #pragma unroll
        for (int i = 0; i < 4; i++)
            #pragma unroll
            for (int j = 0; j < 4; j++) s[i][j] = 0.f;

        #pragma unroll 4
        for (int kk = 0; kk < H_SZ; kk += 4) {
            float4 qv[4], kv[4];
            #pragma unroll
            for (int i = 0; i < 4; i++)
                qv[i] = *(const float4*)&Qs[(ty * 4 + i) * H_SZ + kk];
            #pragma unroll
            for (int u = 0; u < 4; u++)
                kv[u] = *(const float4*)&KVs[(kk + u) * KT_STRIDE + tx * 4];
            #pragma unroll
            for (int i = 0; i < 4; i++) {
                const float* qp = (const float*)&qv[i];
                #pragma unroll
                for (int u = 0; u < 4; u++) {
                    const float* kp = (const float*)&kv[u];
                    float q = qp[u];
                    s[i][0] += q * kp[0];
                    s[i][1] += q * kp[1];
                    s[i][2] += q * kp[2];
                    s[i][3] += q * kp[3];
                }
            }
        }

        // ---- Causal mask (only diagonal tile) ----
        if (kt == qtile) {
            #pragma unroll
            for (int i = 0; i < 4; i++)
                #pragma unroll
                for (int j = 0; j < 4; j++)
                    if (tx * 4 + j > ty * 4 + i) s[i][j] = -1e30f;
        }

        // ---- Online softmax update ----
        #pragma unroll
        for (int i = 0; i < 4; i++) {
            float mx = fmaxf(fmaxf(s[i][0], s[i][1]), fmaxf(s[i][2], s[i][3]));
            #pragma unroll
            for (int o = 1; o < 16; o <<= 1)
                mx = fmaxf(mx, __shfl_xor_sync(0xffffffffu, mx, o));
            float m_new = fmaxf(m_i[i], mx);
            float alpha = __expf(m_i[i] - m_new);
            float rs = 0.f;
            #pragma unroll
            for (int j = 0; j < 4; j++) {
                float p = __expf(s[i][j] - m_new);
                s[i][j] = p;
                rs += p;
            }
            #pragma unroll
            for (int o = 1; o < 16; o <<= 1)
                rs += __shfl_xor_sync(0xffffffffu, rs, o);
            l_i[i] = l_i[i] * alpha + rs;
            m_i[i] = m_new;
            #pragma unroll
            for (int j = 0; j < 8; j++) acc[i][j] *= alpha;
            *(float4*)&Ps[(ty * 4 + i) * P_STRIDE + tx * 4] = *(float4*)&s[i][0];
        }
        __syncthreads();  // Ps fully written; Kt reads done -> safe to overwrite KVs

        // ---- Load V tile (natural layout) ----
        {
            const float* vbase = g_v + (size_t)(b * T_SZ + kt * BN) * H_SZ;
            #pragma unroll
            for (int i = 0; i < 8; i++) {
                int r = i * 8 + (tid >> 5);
                int c = (tid & 31) * 4;
                *(float4*)&KVs[r * H_SZ + c] =
                    *(const float4*)&vbase[(size_t)r * H_SZ + c];
            }
        }
        __syncthreads();

        // ---- O += P * V  (4 rows x 8 cols per thread) ----
        #pragma unroll 2
        for (int k = 0; k < BN; k++) {
            float4 v0 = *(const float4*)&KVs[k * H_SZ + tx * 8];
            float4 v1 = *(const float4*)&KVs[k * H_SZ + tx * 8 + 4];
            #pragma unroll
            for (int i = 0; i < 4; i++) {
                float p = Ps[(ty * 4 + i) * P_STRIDE + k];
                acc[i][0] += p * v0.x; acc[i][1] += p * v0.y;
                acc[i][2] += p * v0.z; acc[i][3] += p * v0.w;
                acc[i][4] += p * v1.x; acc[i][5] += p * v1.y;
                acc[i][6] += p * v1.z; acc[i][7] += p * v1.w;
            }
        }
    }

    // ---- Finalize: divide by l, write out ----
    float* obase = out + (size_t)(b * T_SZ + q0) * H_SZ;
    #pragma unroll
    for (int i = 0; i < 4; i++) {
        float linv = 1.0f / l_i[i];
        int r = ty * 4 + i;
        float4 o0, o1;
        o0.x = acc[i][0] * linv; o0.y = acc[i][1] * linv;
        o0.z = acc[i][2] * linv; o0.w = acc[i][3] * linv;
        o1.x = acc[i][4] * linv; o1.y = acc[i][5] * linv;
        o1.z = acc[i][6] * linv; o1.w = acc[i][7] * linv;
        *(float4*)&obase[(size_t)r * H_SZ + tx * 8]     = o0;
        *(float4*)&obase[(size_t)r * H_SZ + tx * 8 + 4] = o1;
    }
}

// ---------------------------------------------------------------------------
// Inputs (metadata order): embedded_data, Wq, bq, Wk, bk, Wv, bv
// Output: [B, T, H] float32
// ---------------------------------------------------------------------------
extern "C" void kernel_launch(void* const* d_in, const int* in_sizes, int n_in,
                              void* d_out, int out_size)
{
    const float* X  = (const float*)d_in[0];
    const float* Wq = (const float*)d_in[1];
    const float* bq = (const float*)d_in[2];
    const float* Wk = (const float*)d_in[3];
    const float* bk = (const float*)d_in[4];
    const float* Wv = (const float*)d_in[5];
    const float* bv = (const float*)d_in[6];
    float* out = (float*)d_out;

    // Idempotent, deterministic, not a stream op -> capture-safe.
    cudaFuncSetAttribute(attn_kernel,
                         cudaFuncAttributeMaxDynamicSharedMemorySize,
                         ATTN_SMEM_BYTES);

    dim3 g1(M_TOT / 128, 3);
    qkv_kernel<<<g1, 256>>>(X, Wq, bq, Wk, bk, Wv, bv);

    dim3 g2(T_SZ / BM, B_SZ);
    attn_kernel<<<g2, 256, ATTN_SMEM_BYTES>>>(out);
}

// round 8
// speedup vs baseline: 1.4593x; 1.4593x over previous
#include <cuda_runtime.h>

// Problem constants
#define B_SZ 8
#define T_SZ 2048
#define C_SZ 1024
#define H_SZ 128
#define M_TOT (B_SZ * T_SZ)   // 16384 rows for QKV GEMM

// Scratch for projected q, k, v (allocation-free rule: __device__ globals)
__device__ float g_q[M_TOT * H_SZ];
__device__ float g_k[M_TOT * H_SZ];
__device__ float g_v[M_TOT * H_SZ];

// ---------------------------------------------------------------------------
// tf32 helpers
// ---------------------------------------------------------------------------
__device__ __forceinline__ unsigned f32_to_tf32(float x) {
    unsigned u;
    asm volatile("cvt.rna.tf32.f32 %0, %1;" : "=r"(u) : "f"(x));
    return u;
}

__device__ __forceinline__ void split_tf32(float x, unsigned& h, unsigned& l) {
    h = f32_to_tf32(x);
    l = f32_to_tf32(x - __uint_as_float(h));
}

__device__ __forceinline__ void mma_tf32(float d[4], const unsigned a[4],
                                         const unsigned b0, const unsigned b1) {
    asm volatile(
        "mma.sync.aligned.m16n8k8.row.col.f32.tf32.tf32.f32 "
        "{%0,%1,%2,%3}, {%4,%5,%6,%7}, {%8,%9}, {%0,%1,%2,%3};\n"
        : "+f"(d[0]), "+f"(d[1]), "+f"(d[2]), "+f"(d[3])
        : "r"(a[0]), "r"(a[1]), "r"(a[2]), "r"(a[3]), "r"(b0), "r"(b1));
}

// ===========================================================================
// Tensor-core QKV projection (3xTF32 compensated): out = X @ W + b
// CTA: 256 threads (8 warps), tile 128(M) x 128(N), K-chunk 32.
// Warp grid 4(m) x 2(n).  mma.m16n8k8.row.col tf32.
// ===========================================================================
#define XS_STRIDE 36    // (36*gid+tig)%32 = (4*gid+tig)%32 -> A-frag conflict-free
#define WS_STRIDE 136   // (136*tig+gid)%32 = (8*tig+gid)%32 -> B-frag conflict-free
#define XS_FLOATS (128 * XS_STRIDE)
#define WS_FLOATS (32 * WS_STRIDE)
#define QKV_SMEM_BYTES ((2 * XS_FLOATS + 2 * WS_FLOATS) * 4)

__global__ __launch_bounds__(256) void qkv_kernel(
    const float* __restrict__ X,
    const float* __restrict__ Wq, const float* __restrict__ bq,
    const float* __restrict__ Wk, const float* __restrict__ bk,
    const float* __restrict__ Wv, const float* __restrict__ bv)
{
    extern __shared__ unsigned smu[];
    unsigned* Xh = smu;                    // [128][36] tf32 hi
    unsigned* Xl = Xh + XS_FLOATS;         // [128][36] tf32 lo
    unsigned* Wh = Xl + XS_FLOATS;         // [32][136] tf32 hi
    unsigned* Wl = Wh + WS_FLOATS;         // [32][136] tf32 lo

    const float* W;
    const float* bias;
    float* out;
    if (blockIdx.y == 0)      { W = Wq; bias = bq; out = g_q; }
    else if (blockIdx.y == 1) { W = Wk; bias = bk; out = g_k; }
    else                      { W = Wv; bias = bv; out = g_v; }

    const int tid  = threadIdx.x;
    const int wid  = tid >> 5;
    const int lane = tid & 31;
    const int gid  = lane >> 2;
    const int tig  = lane & 3;
    const int wm   = wid >> 1;    // warp m 0..3
    const int wn   = wid & 1;     // warp n 0..1
    const int m0   = blockIdx.x * 128;

    float d[2][8][4];
    #pragma unroll
    for (int mb = 0; mb < 2; mb++)
        #pragma unroll
        for (int nb = 0; nb < 8; nb++)
            #pragma unroll
            for (int i = 0; i < 4; i++) d[mb][nb][i] = 0.f;

    const int xrow = tid >> 1;            // 0..127
    const int xkg  = (tid & 1) * 16;      // 0 or 16
    const int wkr  = tid >> 3;            // 0..31
    const int wng  = (tid & 7) * 16;      // 0..112

    for (int k0 = 0; k0 < C_SZ; k0 += 32) {
        __syncthreads();
        // Stage X tile (128 x 32) as tf32 hi/lo
        #pragma unroll
        for (int i = 0; i < 4; i++) {
            int kk = xkg + i * 4;
            float4 xv = *(const float4*)&X[(size_t)(m0 + xrow) * C_SZ + k0 + kk];
            float vals[4] = {xv.x, xv.y, xv.z, xv.w};
            unsigned h4[4], l4[4];
            #pragma unroll
            for (int j = 0; j < 4; j++) split_tf32(vals[j], h4[j], l4[j]);
            *(uint4*)&Xh[xrow * XS_STRIDE + kk] = *(uint4*)h4;
            *(uint4*)&Xl[xrow * XS_STRIDE + kk] = *(uint4*)l4;
        }
        // Stage W tile (32 x 128) as tf32 hi/lo
        #pragma unroll
        for (int i = 0; i < 4; i++) {
            int nn = wng + i * 4;
            float4 wv = *(const float4*)&W[(size_t)(k0 + wkr) * H_SZ + nn];
            float vals[4] = {wv.x, wv.y, wv.z, wv.w};
            unsigned h4[4], l4[4];
            #pragma unroll
            for (int j = 0; j < 4; j++) split_tf32(vals[j], h4[j], l4[j]);
            *(uint4*)&Wh[wkr * WS_STRIDE + nn] = *(uint4*)h4;
            *(uint4*)&Wl[wkr * WS_STRIDE + nn] = *(uint4*)l4;
        }
        __syncthreads();

        #pragma unroll
        for (int ks = 0; ks < 4; ks++) {
            const int kc = ks * 8;
            unsigned ah[2][4], al[2][4];
            #pragma unroll
            for (int mb = 0; mb < 2; mb++) {
                int r0 = wm * 32 + mb * 16 + gid;
                ah[mb][0] = Xh[r0 * XS_STRIDE + kc + tig];
                ah[mb][1] = Xh[(r0 + 8) * XS_STRIDE + kc + tig];
                ah[mb][2] = Xh[r0 * XS_STRIDE + kc + tig + 4];
                ah[mb][3] = Xh[(r0 + 8) * XS_STRIDE + kc + tig + 4];
                al[mb][0] = Xl[r0 * XS_STRIDE + kc + tig];
                al[mb][1] = Xl[(r0 + 8) * XS_STRIDE + kc + tig];
                al[mb][2] = Xl[r0 * XS_STRIDE + kc + tig + 4];
                al[mb][3] = Xl[(r0 + 8) * XS_STRIDE + kc + tig + 4];
            }
            #pragma unroll
            for (int nb = 0; nb < 8; nb++) {
                int n = wn * 64 + nb * 8 + gid;
                unsigned bh0 = Wh[(kc + tig) * WS_STRIDE + n];
                unsigned bh1 = Wh[(kc + tig + 4) * WS_STRIDE + n];
                unsigned bl0 = Wl[(kc + tig) * WS_STRIDE + n];
                unsigned bl1 = Wl[(kc + tig + 4) * WS_STRIDE + n];
                #pragma unroll
                for (int mb = 0; mb < 2; mb++) {
                    mma_tf32(d[mb][nb], ah[mb], bh0, bh1);  // hi*hi
                    mma_tf32(d[mb][nb], ah[mb], bl0, bl1);  // hi*lo
                    mma_tf32(d[mb][nb], al[mb], bh0, bh1);  // lo*hi
                }
            }
        }
    }

    #pragma unroll
    for (int nb = 0; nb < 8; nb++) {
        int col = wn * 64 + nb * 8 + 2 * tig;
        float bx = bias[col];
        float by = bias[col + 1];
        #pragma unroll
        for (int mb = 0; mb < 2; mb++) {
            int row0 = m0 + wm * 32 + mb * 16 + gid;
            float2 o0 = make_float2(d[mb][nb][0] + bx, d[mb][nb][1] + by);
            float2 o1 = make_float2(d[mb][nb][2] + bx, d[mb][nb][3] + by);
            *(float2*)&out[(size_t)row0 * H_SZ + col]       = o0;
            *(float2*)&out[(size_t)(row0 + 8) * H_SZ + col] = o1;
        }
    }
}

// ===========================================================================
// Tensor-core flash attention (3xTF32 compensated), online softmax.
// CTA: 128 threads (4 warps). Warp w owns S rows [16w,16w+16).
// Each CTA processes q-tile PAIR (x, 31-x): uniform 34 K-iterations.
// Grid (16, 8) = 128 CTAs < 148 SMs -> 1 CTA/SM regardless of smem, so ALL
// operands are staged PRE-SPLIT (tf32 hi/lo planes); mainloop = pure LDS+MMA.
// Smem (uint):
//   Qh/Ql[64][132], Kh/Kl[64][132] (unioned with Ph/Pl[64][68]), Vh/Vl[64][136]
//   Q/K stride 132 (=4 mod 32): A/B frag loads conflict-free
//   V   stride 136 (=8 mod 32): B frag loads conflict-free
//   P   stride  68 (=4 mod 32): A frag loads conflict-free
// Total 204,800 B (< 227 KB cap).
// ===========================================================================
#define ABM 64
#define Q_STRIDE 132
#define K_STRIDE 132
#define V_STRIDE 136
#define P_STRIDE 68
#define QK_PLANE (ABM * Q_STRIDE)     // 8448 u32
#define V_PLANE  (ABM * V_STRIDE)     // 8704 u32
#define ATTN_SMEM_BYTES ((4 * QK_PLANE + 2 * V_PLANE) * 4)   // 204,800 B

__global__ __launch_bounds__(128) void attn_kernel(float* __restrict__ out)
{
    extern __shared__ unsigned smua[];
    unsigned* Qh = smua;                 // [64][132]
    unsigned* Ql = Qh + QK_PLANE;        // [64][132]
    unsigned* Kh = Ql + QK_PLANE;        // [64][132]
    unsigned* Kl = Kh + QK_PLANE;        // [64][132]
    unsigned* Vh = Kl + QK_PLANE;        // [64][136]
    unsigned* Vl = Vh + V_PLANE;         // [64][136]
    unsigned* Ph = Kh;                   // [64][68]  (K dead after S)
    unsigned* Pl = Kl;                   // [64][68]

    const int tid  = threadIdx.x;
    const int w    = tid >> 5;
    const int lane = tid & 31;
    const int gid  = lane >> 2;
    const int tig  = lane & 3;
    const int b    = blockIdx.y;
    const float scale = 1.0f / 32.0f;    // C^-0.5

    const int ldrow = tid >> 1;          // 0..63 (cooperative tile loads)
    const int ldc0  = (tid & 1) * 64;

    #pragma unroll 1
    for (int half = 0; half < 2; half++) {
        const int qt = (half == 0) ? (int)blockIdx.x : 31 - (int)blockIdx.x;
        const int q0 = qt * ABM;

        // ---- Load Q tile: scale, split hi/lo once per q-tile ----
        {
            const float* qb = g_q + ((size_t)b * T_SZ + q0) * H_SZ;
            #pragma unroll
            for (int i = 0; i < 16; i++) {
                float4 v = *(const float4*)&qb[(size_t)ldrow * H_SZ + ldc0 + 4 * i];
                float vals[4] = {v.x * scale, v.y * scale, v.z * scale, v.w * scale};
                unsigned h4[4], l4[4];
                #pragma unroll
                for (int j = 0; j < 4; j++) split_tf32(vals[j], h4[j], l4[j]);
                *(uint4*)&Qh[ldrow * Q_STRIDE + ldc0 + 4 * i] = *(uint4*)h4;
                *(uint4*)&Ql[ldrow * Q_STRIDE + ldc0 + 4 * i] = *(uint4*)l4;
            }
        }

        float m_i[2] = {-1e30f, -1e30f};
        float l_i[2] = {0.f, 0.f};
        float oacc[16][4];
        #pragma unroll
        for (int nb = 0; nb < 16; nb++)
            #pragma unroll
            for (int i = 0; i < 4; i++) oacc[nb][i] = 0.f;

        const int r0 = w * 16 + gid;   // thread's first S/O row within tile

        for (int kt = 0; kt <= qt; kt++) {
            __syncthreads();   // prev PV done reading Ph/Pl/V; Q visible on iter 0

            // ---- Stage K and V tiles pre-split hi/lo ----
            {
                const float* kb = g_k + ((size_t)b * T_SZ + (size_t)kt * ABM) * H_SZ;
                const float* vb = g_v + ((size_t)b * T_SZ + (size_t)kt * ABM) * H_SZ;
                #pragma unroll
                for (int i = 0; i < 16; i++) {
                    float4 v = *(const float4*)&kb[(size_t)ldrow * H_SZ + ldc0 + 4 * i];
                    float vals[4] = {v.x, v.y, v.z, v.w};
                    unsigned h4[4], l4[4];
                    #pragma unroll
                    for (int j = 0; j < 4; j++) split_tf32(vals[j], h4[j], l4[j]);
                    *(uint4*)&Kh[ldrow * K_STRIDE + ldc0 + 4 * i] = *(uint4*)h4;
                    *(uint4*)&Kl[ldrow * K_STRIDE + ldc0 + 4 * i] = *(uint4*)l4;
                }
                #pragma unroll
                for (int i = 0; i < 16; i++) {
                    float4 v = *(const float4*)&vb[(size_t)ldrow * H_SZ + ldc0 + 4 * i];
                    float vals[4] = {v.x, v.y, v.z, v.w};
                    unsigned h4[4], l4[4];
                    #pragma unroll
                    for (int j = 0; j < 4; j++) split_tf32(vals[j], h4[j], l4[j]);
                    *(uint4*)&Vh[ldrow * V_STRIDE + ldc0 + 4 * i] = *(uint4*)h4;
                    *(uint4*)&Vl[ldrow * V_STRIDE + ldc0 + 4 * i] = *(uint4*)l4;
                }
            }
            __syncthreads();

            // ---- S = Q * K^T  (warp: m16 x n64, K-dim 128 = 16 k-steps) ----
            float sacc[8][4];
            #pragma unroll
            for (int nb = 0; nb < 8; nb++)
                #pragma unroll
                for (int i = 0; i < 4; i++) sacc[nb][i] = 0.f;

            #pragma unroll 4
            for (int ks = 0; ks < 16; ks++) {
                const int kc = ks * 8;
                unsigned ah[4], al[4];
                ah[0] = Qh[r0 * Q_STRIDE + kc + tig];
                ah[1] = Qh[(r0 + 8) * Q_STRIDE + kc + tig];
                ah[2] = Qh[r0 * Q_STRIDE + kc + tig + 4];
                ah[3] = Qh[(r0 + 8) * Q_STRIDE + kc + tig + 4];
                al[0] = Ql[r0 * Q_STRIDE + kc + tig];
                al[1] = Ql[(r0 + 8) * Q_STRIDE + kc + tig];
                al[2] = Ql[r0 * Q_STRIDE + kc + tig + 4];
                al[3] = Ql[(r0 + 8) * Q_STRIDE + kc + tig + 4];
                #pragma unroll
                for (int nb = 0; nb < 8; nb++) {
                    const int n = nb * 8 + gid;
                    unsigned bh0 = Kh[n * K_STRIDE + kc + tig];
                    unsigned bh1 = Kh[n * K_STRIDE + kc + tig + 4];
                    unsigned bl0 = Kl[n * K_STRIDE + kc + tig];
                    unsigned bl1 = Kl[n * K_STRIDE + kc + tig + 4];
                    mma_tf32(sacc[nb], ah, bh0, bh1);
                    mma_tf32(sacc[nb], ah, bl0, bl1);
                    mma_tf32(sacc[nb], al, bh0, bh1);
                }
            }

            // ---- Causal mask (diagonal tile only; local rows vs local cols) ----
            if (kt == qt) {
                #pragma unroll
                for (int nb = 0; nb < 8; nb++) {
                    int cb = nb * 8 + 2 * tig;
                    if (cb     > r0)     sacc[nb][0] = -1e30f;
                    if (cb + 1 > r0)     sacc[nb][1] = -1e30f;
                    if (cb     > r0 + 8) sacc[nb][2] = -1e30f;
                    if (cb + 1 > r0 + 8) sacc[nb][3] = -1e30f;
                }
            }

            // ---- Online softmax (rows r0 and r0+8; reduce over quad lanes) ----
            {
                float mx0 = -1e30f, mx1 = -1e30f;
                #pragma unroll
                for (int nb = 0; nb < 8; nb++) {
                    mx0 = fmaxf(mx0, fmaxf(sacc[nb][0], sacc[nb][1]));
                    mx1 = fmaxf(mx1, fmaxf(sacc[nb][2], sacc[nb][3]));
                }
                mx0 = fmaxf(mx0, __shfl_xor_sync(0xffffffffu, mx0, 1));
                mx0 = fmaxf(mx0, __shfl_xor_sync(0xffffffffu, mx0, 2));
                mx1 = fmaxf(mx1, __shfl_xor_sync(0xffffffffu, mx1, 1));
                mx1 = fmaxf(mx1, __shfl_xor_sync(0xffffffffu, mx1, 2));

                float mn0 = fmaxf(m_i[0], mx0);
                float mn1 = fmaxf(m_i[1], mx1);
                float al0 = __expf(m_i[0] - mn0);
                float al1 = __expf(m_i[1] - mn1);

                float rs0 = 0.f, rs1 = 0.f;
                #pragma unroll
                for (int nb = 0; nb < 8; nb++) {
                    sacc[nb][0] = __expf(sacc[nb][0] - mn0); rs0 += sacc[nb][0];
                    sacc[nb][1] = __expf(sacc[nb][1] - mn0); rs0 += sacc[nb][1];
                    sacc[nb][2] = __expf(sacc[nb][2] - mn1); rs1 += sacc[nb][2];
                    sacc[nb][3] = __expf(sacc[nb][3] - mn1); rs1 += sacc[nb][3];
                }
                rs0 += __shfl_xor_sync(0xffffffffu, rs0, 1);
                rs0 += __shfl_xor_sync(0xffffffffu, rs0, 2);
                rs1 += __shfl_xor_sync(0xffffffffu, rs1, 1);
                rs1 += __shfl_xor_sync(0xffffffffu, rs1, 2);

                l_i[0] = l_i[0] * al0 + rs0;  m_i[0] = mn0;
                l_i[1] = l_i[1] * al1 + rs1;  m_i[1] = mn1;

                #pragma unroll
                for (int nb = 0; nb < 16; nb++) {
                    oacc[nb][0] *= al0; oacc[nb][1] *= al0;
                    oacc[nb][2] *= al1; oacc[nb][3] *= al1;
                }
            }

            __syncthreads();   // ALL warps done reading Kh/Kl -> safe to write P

            // ---- Write P pre-split hi/lo (unioned into K planes) ----
            #pragma unroll
            for (int nb = 0; nb < 8; nb++) {
                int cb = nb * 8 + 2 * tig;
                unsigned h0, l0, h1, l1;
                split_tf32(sacc[nb][0], h0, l0);
                split_tf32(sacc[nb][1], h1, l1);
                *(uint2*)&Ph[r0 * P_STRIDE + cb] = make_uint2(h0, h1);
                *(uint2*)&Pl[r0 * P_STRIDE + cb] = make_uint2(l0, l1);
                split_tf32(sacc[nb][2], h0, l0);
                split_tf32(sacc[nb][3], h1, l1);
                *(uint2*)&Ph[(r0 + 8) * P_STRIDE + cb] = make_uint2(h0, h1);
                *(uint2*)&Pl[(r0 + 8) * P_STRIDE + cb] = make_uint2(l0, l1);
            }
            __syncthreads();   // P visible to all warps

            // ---- O += P * V  (warp: m16 x n128, K-dim 64 = 8 k-steps) ----
            #pragma unroll 4
            for (int ks = 0; ks < 8; ks++) {
                const int kc = ks * 8;
                unsigned ah[4], al[4];
                ah[0] = Ph[r0 * P_STRIDE + kc + tig];
                ah[1] = Ph[(r0 + 8) * P_STRIDE + kc + tig];
                ah[2] = Ph[r0 * P_STRIDE + kc + tig + 4];
                ah[3] = Ph[(r0 + 8) * P_STRIDE + kc + tig + 4];
                al[0] = Pl[r0 * P_STRIDE + kc + tig];
                al[1] = Pl[(r0 + 8) * P_STRIDE + kc + tig];
                al[2] = Pl[r0 * P_STRIDE + kc + tig + 4];
                al[3] = Pl[(r0 + 8) * P_STRIDE + kc + tig + 4];
                #pragma unroll
                for (int nb = 0; nb < 16; nb++) {
                    const int n = nb * 8 + gid;
                    unsigned bh0 = Vh[(kc + tig) * V_STRIDE + n];
                    unsigned bh1 = Vh[(kc + tig + 4) * V_STRIDE + n];
                    unsigned bl0 = Vl[(kc + tig) * V_STRIDE + n];
                    unsigned bl1 = Vl[(kc + tig + 4) * V_STRIDE + n];
                    mma_tf32(oacc[nb], ah, bh0, bh1);
                    mma_tf32(oacc[nb], ah, bl0, bl1);
                    mma_tf32(oacc[nb], al, bh0, bh1);
                }
            }
        }  // kt

        // ---- Epilogue: divide by l, write out ----
        {
            float inv0 = 1.0f / l_i[0];
            float inv1 = 1.0f / l_i[1];
            float* ob = out + ((size_t)b * T_SZ + q0) * H_SZ;
            #pragma unroll
            for (int nb = 0; nb < 16; nb++) {
                int col = nb * 8 + 2 * tig;
                *(float2*)&ob[(size_t)r0 * H_SZ + col] =
                    make_float2(oacc[nb][0] * inv0, oacc[nb][1] * inv0);
                *(float2*)&ob[(size_t)(r0 + 8) * H_SZ + col] =
                    make_float2(oacc[nb][2] * inv1, oacc[nb][3] * inv1);
            }
        }
    }  // half
}

// ---------------------------------------------------------------------------
// Inputs (metadata order): embedded_data, Wq, bq, Wk, bk, Wv, bv
// Output: [B, T, H] float32
// ---------------------------------------------------------------------------
extern "C" void kernel_launch(void* const* d_in, const int* in_sizes, int n_in,
                              void* d_out, int out_size)
{
    const float* X  = (const float*)d_in[0];
    const float* Wq = (const float*)d_in[1];
    const float* bq = (const float*)d_in[2];
    const float* Wk = (const float*)d_in[3];
    const float* bk = (const float*)d_in[4];
    const float* Wv = (const float*)d_in[5];
    const float* bv = (const float*)d_in[6];
    float* out = (float*)d_out;

    // Idempotent, deterministic, not stream ops -> capture-safe.
    cudaFuncSetAttribute(qkv_kernel,
                         cudaFuncAttributeMaxDynamicSharedMemorySize,
                         QKV_SMEM_BYTES);
    cudaFuncSetAttribute(attn_kernel,
                         cudaFuncAttributeMaxDynamicSharedMemorySize,
                         ATTN_SMEM_BYTES);

    dim3 g1(M_TOT / 128, 3);
    qkv_kernel<<<g1, 256, QKV_SMEM_BYTES>>>(X, Wq, bq, Wk, bk, Wv, bv);

    dim3 g2(16, B_SZ);   // q-tile pairs (x, 31-x) x batch
    attn_kernel<<<g2, 128, ATTN_SMEM_BYTES>>>(out);
}